// round 6
// baseline (speedup 1.0000x reference)
#include <cuda_runtime.h>

// Reference math: dx = 0  =>  s^2 = -dt^2 <= 0 everywhere  =>  spacelike_mask == 0
// => penalty == 0 => total_loss = base_loss + 0.01 * 0 = base_loss (bit-exact in fp32).
// attn_weights (d_in[0], ~302M floats) is dead input; live dependence is 4 bytes.
//
// FINAL (converged): captured graph = one SM-path kernel node copying the scalar.
// Measured floor 18 ticks (4.608 µs) on a 256 ns-quantized timer:
//   kernel node (SM): {4.864, 4.608} µs  — no tail        <- this variant
//   memcpy node (CE): {4.608, 4.864, 6.912} µs — CE-path tail observed
// Cross-hold variance (±1-9 ticks) exceeds all remaining design deltas.
// No removable node (d_out poisoned pre-timing), no cheaper node type,
// no fewer bytes, no exploitable parallelism. Session converged.

__global__ __launch_bounds__(32)
void spacetime_loss_copy(const float* __restrict__ base_loss,
                         float* __restrict__ out) {
    if (threadIdx.x == 0) out[0] = base_loss[0];
}

extern "C" void kernel_launch(void* const* d_in, const int* in_sizes, int n_in,
                              void* d_out, int out_size) {
    // d_in[1] = base_loss scalar f32; d_out[0] = total_loss f32
    spacetime_loss_copy<<<1, 32>>>((const float*)d_in[1], (float*)d_out);
}

// round 7
// speedup vs baseline: 1.0629x; 1.0629x over previous
#include <cuda_runtime.h>

// Reference math: dx = 0  =>  s^2 = -dt^2 <= 0 everywhere  =>  spacelike_mask == 0
// => penalty == 0 => total_loss = base_loss + 0.01 * 0 = base_loss (bit-exact in fp32).
// attn_weights (d_in[0], ~302M floats) is dead input; live dependence is 4 bytes.
//
// FINAL (converged): captured graph = one SM-path kernel node copying the scalar.
// Measured floor 18 ticks (4.608 µs) on a 256 ns-quantized timer:
//   kernel node (SM): {4.864, 4.608} µs  — no tail        <- this variant
//   memcpy node (CE): {4.608, 4.864, 6.912} µs — CE-path tail observed
// Cross-hold variance (±1-9 ticks) exceeds all remaining design deltas.
// No removable node (d_out poisoned pre-timing), no cheaper node type,
// no fewer bytes, no exploitable parallelism. Session converged.

__global__ __launch_bounds__(32)
void spacetime_loss_copy(const float* __restrict__ base_loss,
                         float* __restrict__ out) {
    if (threadIdx.x == 0) out[0] = base_loss[0];
}

extern "C" void kernel_launch(void* const* d_in, const int* in_sizes, int n_in,
                              void* d_out, int out_size) {
    // d_in[1] = base_loss scalar f32; d_out[0] = total_loss f32
    spacetime_loss_copy<<<1, 32>>>((const float*)d_in[1], (float*)d_out);
}